// round 4
// baseline (speedup 1.0000x reference)
#include <cuda_runtime.h>

// Problem constants
#define NN 100000
#define EE 1600000

// ---------------- scratch (device globals; no allocation allowed) ----------
__device__ __align__(16) float g_ae2[EE * 4];    // layer-2 edge logit term   (25.6 MB)
__device__ __align__(16) float g_xp[NN * 64];    // per-node projected feats  (25.6 MB)
__device__ __align__(16) float g_acc[NN * 64];   // weighted aggregation      (25.6 MB)
__device__ float g_asrc[NN * 4];
__device__ float g_adst[NN * 4];
__device__ float g_denom[NN * 4];
__device__ float g_P[512];                        // folded [64][8]: cols 0-3 L1, 4-7 L2

// ---------------------------------------------------------------------------
// edge_index dtype hedge: reference says int64, harness doc says int32.
// For int64 data (all values < 2^31, little-endian) the odd 32-bit words are
// all zero. Detect once per thread from the first 4 entries (L1 broadcast).
// ---------------------------------------------------------------------------
__device__ __forceinline__ bool ei_is64(const int* __restrict__ ei) {
    return (ei[1] | ei[3] | ei[5] | ei[7]) == 0;
}
__device__ __forceinline__ int ei_load(const int* __restrict__ ei, long long pos, bool is64) {
    return is64 ? ei[pos * 2] : ei[pos];
}

// ---------------------------------------------------------------------------
// Fold the edge-feature path:  a_e1 = ea @ P1,  a_e2 = ea @ P2
//   P1 = We1 @ A1        (A1[k][h] = att_edge1[h][k-16h] on head-block diag)
//   P2 = We1 @ We2 @ A2
// ---------------------------------------------------------------------------
__global__ void precompute_kernel(const float* __restrict__ We1,
                                  const float* __restrict__ We2,
                                  const float* __restrict__ ate1,
                                  const float* __restrict__ ate2) {
    int j = threadIdx.x;  // 0..63
    __shared__ float A2p[64 * 4];
#pragma unroll
    for (int h = 0; h < 4; h++) {
        float s = 0.f;
#pragma unroll
        for (int c = 0; c < 16; c++) s += We2[j * 64 + h * 16 + c] * ate2[h * 16 + c];
        A2p[j * 4 + h] = s;
    }
    __syncthreads();
#pragma unroll
    for (int h = 0; h < 4; h++) {
        float s = 0.f;
#pragma unroll
        for (int c = 0; c < 16; c++) s += We1[j * 64 + h * 16 + c] * ate1[h * 16 + c];
        g_P[j * 8 + h] = s;
    }
#pragma unroll
    for (int h = 0; h < 4; h++) {
        float s = 0.f;
        for (int k = 0; k < 64; k++) s += We1[j * 64 + k] * A2p[k * 4 + h];
        g_P[j * 8 + 4 + h] = s;
    }
}

__global__ void zero_kernel() {
    int i = blockIdx.x * 256 + threadIdx.x;
    if (i < NN * 64) g_acc[i] = 0.f;
    if (i < NN * 4) g_denom[i] = 0.f;
}

// ---------------------------------------------------------------------------
// Node kernel: xp = relu?(input) @ W  [+ per-head att dot products]
// MODE 0: input = raw x rows (len IN)         -> g_xp, g_asrc, g_adst
// MODE 1: input = relu(g_acc / g_denom)       -> g_xp, g_asrc, g_adst
// MODE 2: input = relu(g_acc / g_denom), out = input @ W + bias -> outp
// 256 threads = 4 node-groups of 64; thread t owns output channel t.
// ---------------------------------------------------------------------------
template <int IN, int MODE>
__global__ void __launch_bounds__(256) node_kernel(const float* __restrict__ xin,
                                                   const float* __restrict__ W,
                                                   const float* __restrict__ attS,
                                                   const float* __restrict__ attD,
                                                   const float* __restrict__ bias,
                                                   float* __restrict__ outp) {
    __shared__ float Ws[IN * 64];
    __shared__ float xs[4][IN];
    __shared__ float aSs[64], aDs[64];
    for (int i = threadIdx.x; i < IN * 64; i += 256) Ws[i] = W[i];
    if (MODE < 2 && threadIdx.x < 64) {
        aSs[threadIdx.x] = attS[threadIdx.x];
        aDs[threadIdx.x] = attD[threadIdx.x];
    }
    int g = threadIdx.x >> 6, t = threadIdx.x & 63;
    int n = blockIdx.x * 4 + g;
    bool valid = n < NN;
    if (valid) {
        if (MODE == 0) {
            for (int k = t; k < IN; k += 64) xs[g][k] = xin[(size_t)n * IN + k];
        } else {
            float den = g_denom[n * 4 + (t >> 4)];
            float v = g_acc[n * 64 + t] / fmaxf(den, 1e-16f);
            xs[g][t] = fmaxf(v, 0.f);
        }
    }
    __syncthreads();
    if (!valid) return;
    float acc = 0.f;
#pragma unroll
    for (int k = 0; k < IN; k++) acc += xs[g][k] * Ws[k * 64 + t];
    if (MODE == 2) {
        outp[(size_t)n * 64 + t] = acc + bias[t];
    } else {
        g_xp[n * 64 + t] = acc;
        float r1 = acc * aSs[t];
        float r2 = acc * aDs[t];
#pragma unroll
        for (int o = 8; o; o >>= 1) {
            r1 += __shfl_xor_sync(0xffffffffu, r1, o);
            r2 += __shfl_xor_sync(0xffffffffu, r2, o);
        }
        if ((t & 15) == 0) {
            g_asrc[n * 4 + (t >> 4)] = r1;
            g_adst[n * 4 + (t >> 4)] = r2;
        }
    }
}

// ---------------------------------------------------------------------------
// Fused edge pass, layer 1. One warp per edge:
//  - stream edge_attr[e] (192 floats), reduce mean over 3 -> ea[64] (in smem)
//  - ea @ P gives a_e1[4] (used now) and a_e2[4] (stored for layer 2)
//  - w = exp(leakyrelu(asrc[src]+adst[dst]+a_e1)); scatter w*xp[src] via red.v4
// ---------------------------------------------------------------------------
__global__ void __launch_bounds__(256) edge_l1_kernel(const float* __restrict__ edge_attr,
                                                      const int* __restrict__ ei) {
    __shared__ float Ps[512];
    __shared__ float eas[8][64];
    for (int i = threadIdx.x; i < 512; i += 256) Ps[i] = g_P[i];
    __syncthreads();
    int wid = threadIdx.x >> 5, lane = threadIdx.x & 31;
    int e = blockIdx.x * 8 + wid;
    if (e >= EE) return;  // whole warp exits together

    const float* ea = edge_attr + (size_t)e * 192;
    float ea1 = (ea[lane] + ea[lane + 64] + ea[lane + 128]) * (1.f / 3.f);
    float ea2 = (ea[lane + 32] + ea[lane + 96] + ea[lane + 160]) * (1.f / 3.f);
    eas[wid][lane] = ea1;
    eas[wid][lane + 32] = ea2;
    __syncwarp();

    // lane -> (h = lane>>2 in 0..7, 16-wide j chunk (lane&3)); 2-shfl reduce
    int h4 = lane >> 2;
    int j0 = (lane & 3) * 16;
    float p = 0.f;
#pragma unroll
    for (int i = 0; i < 16; i++) p += eas[wid][j0 + i] * Ps[(j0 + i) * 8 + h4];
    p += __shfl_xor_sync(0xffffffffu, p, 1);
    p += __shfl_xor_sync(0xffffffffu, p, 2);

    bool is64 = ei_is64(ei);
    int s = ei_load(ei, e, is64);
    int d = ei_load(ei, (long long)EE + e, is64);
    if (lane >= 16) {
        if ((lane & 3) == 0) g_ae2[(size_t)e * 4 + (h4 - 4)] = p;  // layer-2 term
    } else {
        float a = g_asrc[s * 4 + h4] + g_adst[d * 4 + h4] + p;
        a = a > 0.f ? a : 0.2f * a;
        float w = __expf(a);
        float4 v = reinterpret_cast<const float4*>(g_xp)[s * 16 + lane];
        atomicAdd(reinterpret_cast<float4*>(g_acc) + (d * 16 + lane),
                  make_float4(w * v.x, w * v.y, w * v.z, w * v.w));
        if ((lane & 3) == 0) atomicAdd(&g_denom[d * 4 + h4], w);
    }
}

// ---------------------------------------------------------------------------
// Edge pass, layer 2. 16 threads per edge (a_e2 precomputed, no edge_attr read)
// ---------------------------------------------------------------------------
__global__ void __launch_bounds__(256) edge_l2_kernel(const int* __restrict__ ei) {
    int e = blockIdx.x * 16 + (threadIdx.x >> 4);
    int l = threadIdx.x & 15;
    if (e >= EE) return;
    bool is64 = ei_is64(ei);
    int s = ei_load(ei, e, is64);
    int d = ei_load(ei, (long long)EE + e, is64);
    int h = l >> 2;
    float a = g_asrc[s * 4 + h] + g_adst[d * 4 + h] + g_ae2[(size_t)e * 4 + h];
    a = a > 0.f ? a : 0.2f * a;
    float w = __expf(a);
    float4 v = reinterpret_cast<const float4*>(g_xp)[s * 16 + l];
    atomicAdd(reinterpret_cast<float4*>(g_acc) + (d * 16 + l),
              make_float4(w * v.x, w * v.y, w * v.z, w * v.w));
    if (!(l & 3)) atomicAdd(&g_denom[d * 4 + h], w);
}

// ---------------------------------------------------------------------------
extern "C" void kernel_launch(void* const* d_in, const int* in_sizes, int n_in,
                              void* d_out, int out_size) {
    const float* x = (const float*)d_in[0];
    const int* ei = (const int*)d_in[1];
    const float* edge_attr = (const float*)d_in[2];
    const float* W1 = (const float*)d_in[3];
    const float* We1 = (const float*)d_in[4];
    const float* as1 = (const float*)d_in[5];
    const float* ad1 = (const float*)d_in[6];
    const float* ae1 = (const float*)d_in[7];
    const float* W2 = (const float*)d_in[8];
    const float* We2 = (const float*)d_in[9];
    const float* as2 = (const float*)d_in[10];
    const float* ad2 = (const float*)d_in[11];
    const float* ae2 = (const float*)d_in[12];
    const float* Wout = (const float*)d_in[13];
    const float* bout = (const float*)d_in[14];
    float* out = (float*)d_out;

    precompute_kernel<<<1, 64>>>(We1, We2, ae1, ae2);
    node_kernel<128, 0><<<(NN + 3) / 4, 256>>>(x, W1, as1, ad1, nullptr, nullptr);
    zero_kernel<<<(NN * 64 + 255) / 256, 256>>>();
    edge_l1_kernel<<<(EE + 7) / 8, 256>>>(edge_attr, ei);
    node_kernel<64, 1><<<(NN + 3) / 4, 256>>>(nullptr, W2, as2, ad2, nullptr, nullptr);
    zero_kernel<<<(NN * 64 + 255) / 256, 256>>>();
    edge_l2_kernel<<<(EE + 15) / 16, 256>>>(ei);
    node_kernel<64, 2><<<(NN + 3) / 4, 256>>>(nullptr, Wout, nullptr, nullptr, bout, out);
}